// round 2
// baseline (speedup 1.0000x reference)
#include <cuda_runtime.h>

#define NN 20000
#define EE 10000
#define IC 128
#define OC 64
#define BK2 32
#define SPLIT 16
#define BK3 32

// Scratch (no allocations allowed in kernel_launch)
__device__ float g_xt[NN * OC];      // x @ theta        [N, 64]
__device__ float g_edge[EE * OC];    // accumulators     [E, 64]
__device__ float g_de[EE];           // hyperedge degree [E]

// ---------------------------------------------------------------- zero
__global__ void zero_k() {
    int i = blockIdx.x * 256 + threadIdx.x;
    if (i < EE * OC) g_edge[i] = 0.0f;
    if (i < EE)      g_de[i]   = 0.0f;
}

// ---------------------------------------------------------------- xt = x @ theta
__global__ void xt_k(const float* __restrict__ x, const float* __restrict__ th) {
    __shared__ float ths[IC * OC];
    int tid = threadIdx.x;
    #pragma unroll
    for (int i = tid; i < IC * OC; i += 256) ths[i] = th[i];
    __syncthreads();

    int n = blockIdx.x * 4 + (tid >> 6);
    int c = tid & 63;
    const float* xr = x + (size_t)n * IC;
    float acc = 0.0f;
    #pragma unroll 8
    for (int k = 0; k < IC; ++k) acc += xr[k] * ths[k * OC + c];
    g_xt[n * OC + c] = acc;
}

// ---------------------------------------------------------------- pass2: edge_acc += H^T @ xt ; de += colsum(H)
// Split-K over N (SPLIT chunks of k-tiles), atomicAdd into g_edge/g_de.
__global__ void pass2_k(const float* __restrict__ H) {
    __shared__ float Hs[BK2][68];   // [k_local][e_local]
    __shared__ float Xs[BK2][68];   // [k_local][c]

    int tid = threadIdx.x;
    int e0  = blockIdx.x * 64;
    int tx  = tid & 15;             // channel group (4 ch)
    int ty  = tid >> 4;             // edge group (4 edges)

    const int TILES = NN / BK2;                 // 625
    const int TPC   = (TILES + SPLIT - 1) / SPLIT;
    int t0 = blockIdx.y * TPC;
    int t1 = t0 + TPC; if (t1 > TILES) t1 = TILES;

    bool full_e = (e0 + 64 <= EE);

    float acc[4][4];
    #pragma unroll
    for (int i = 0; i < 4; ++i)
        #pragma unroll
        for (int j = 0; j < 4; ++j) acc[i][j] = 0.0f;
    float dloc[4] = {0.0f, 0.0f, 0.0f, 0.0f};

    int lrow = tid >> 4;            // 0..15
    int lcol = tid & 15;            // float4 column

    for (int t = t0; t < t1; ++t) {
        int k0 = t * BK2;
        #pragma unroll
        for (int it = 0; it < 2; ++it) {
            int r = lrow + it * 16;
            // xt tile (always in-bounds: K exact multiple of 32, 64 channels)
            float4 xv = *(const float4*)&g_xt[(k0 + r) * OC + lcol * 4];
            *(float4*)&Xs[r][lcol * 4] = xv;
            // H tile
            int e = e0 + lcol * 4;
            float4 hv;
            if (full_e) {
                hv = *(const float4*)&H[(size_t)(k0 + r) * EE + e];
            } else {
                hv.x = (e + 0 < EE) ? H[(size_t)(k0 + r) * EE + e + 0] : 0.0f;
                hv.y = (e + 1 < EE) ? H[(size_t)(k0 + r) * EE + e + 1] : 0.0f;
                hv.z = (e + 2 < EE) ? H[(size_t)(k0 + r) * EE + e + 2] : 0.0f;
                hv.w = (e + 3 < EE) ? H[(size_t)(k0 + r) * EE + e + 3] : 0.0f;
            }
            *(float4*)&Hs[r][lcol * 4] = hv;
        }
        __syncthreads();

        #pragma unroll
        for (int kk = 0; kk < BK2; ++kk) {
            float a[4], b[4];
            *(float4*)a = *(const float4*)&Hs[kk][ty * 4];
            *(float4*)b = *(const float4*)&Xs[kk][tx * 4];
            #pragma unroll
            for (int i = 0; i < 4; ++i)
                #pragma unroll
                for (int j = 0; j < 4; ++j) acc[i][j] += a[i] * b[j];
            if (tx == 0) {
                #pragma unroll
                for (int i = 0; i < 4; ++i) dloc[i] += a[i];
            }
        }
        __syncthreads();
    }

    #pragma unroll
    for (int i = 0; i < 4; ++i) {
        int e = e0 + ty * 4 + i;
        if (e < EE) {
            #pragma unroll
            for (int j = 0; j < 4; ++j)
                atomicAdd(&g_edge[e * OC + tx * 4 + j], acc[i][j]);
            if (tx == 0) atomicAdd(&g_de[e], dloc[i]);
        }
    }
}

// ---------------------------------------------------------------- edge /= de
__global__ void div_k() {
    int i = blockIdx.x * 256 + threadIdx.x;
    if (i < EE * OC) g_edge[i] /= g_de[i >> 6];
}

// ---------------------------------------------------------------- pass3: out = (H @ edge) / rowsum(H)
__global__ void pass3_k(const float* __restrict__ H, float* __restrict__ out) {
    __shared__ float Ht[BK3][68];   // [k_local][n_local] (transposed)
    __shared__ float Es[BK3][68];   // [k_local][c]
    __shared__ float dn_s[64];

    int tid = threadIdx.x;
    int n0  = blockIdx.x * 64;
    int tx  = tid & 15;             // channel group
    int ty  = tid >> 4;             // node group

    float acc[4][4];
    #pragma unroll
    for (int i = 0; i < 4; ++i)
        #pragma unroll
        for (int j = 0; j < 4; ++j) acc[i][j] = 0.0f;
    float dloc[4] = {0.0f, 0.0f, 0.0f, 0.0f};

    const int KT = (EE + BK3 - 1) / BK3;        // 313

    for (int t = 0; t < KT; ++t) {
        int k0 = t * BK3;

        // Load H tile [64 nodes x 32 k] transposed into Ht[k][n]
        int lrow = tid >> 3;        // 0..31 (node offset per iter)
        int lcol = tid & 7;         // k float4 group
        #pragma unroll
        for (int it = 0; it < 2; ++it) {
            int nl = lrow + it * 32;
            int n  = n0 + nl;
            int kb = k0 + lcol * 4;
            float v[4];
            if (n < NN && kb + 4 <= EE) {
                float4 hv = *(const float4*)&H[(size_t)n * EE + kb];
                v[0] = hv.x; v[1] = hv.y; v[2] = hv.z; v[3] = hv.w;
            } else {
                #pragma unroll
                for (int j = 0; j < 4; ++j)
                    v[j] = (n < NN && kb + j < EE) ? H[(size_t)n * EE + kb + j] : 0.0f;
            }
            #pragma unroll
            for (int j = 0; j < 4; ++j) Ht[lcol * 4 + j][nl] = v[j];
        }

        // Load edge tile [32 k x 64 ch]
        #pragma unroll
        for (int it = 0; it < 2; ++it) {
            int kl = (tid >> 4) + it * 16;
            int k  = k0 + kl;
            float4 ev;
            if (k < EE) ev = *(const float4*)&g_edge[k * OC + (tid & 15) * 4];
            else        ev = make_float4(0.0f, 0.0f, 0.0f, 0.0f);
            *(float4*)&Es[kl][(tid & 15) * 4] = ev;
        }
        __syncthreads();

        #pragma unroll
        for (int kk = 0; kk < BK3; ++kk) {
            float a[4], b[4];
            *(float4*)a = *(const float4*)&Ht[kk][ty * 4];
            *(float4*)b = *(const float4*)&Es[kk][tx * 4];
            #pragma unroll
            for (int i = 0; i < 4; ++i)
                #pragma unroll
                for (int j = 0; j < 4; ++j) acc[i][j] += a[i] * b[j];
            if (tx == 0) {
                #pragma unroll
                for (int i = 0; i < 4; ++i) dloc[i] += a[i];
            }
        }
        __syncthreads();
    }

    if (tx == 0) {
        #pragma unroll
        for (int i = 0; i < 4; ++i) dn_s[ty * 4 + i] = dloc[i];
    }
    __syncthreads();

    #pragma unroll
    for (int i = 0; i < 4; ++i) {
        int n = n0 + ty * 4 + i;
        if (n < NN) {
            float inv = 1.0f / dn_s[ty * 4 + i];
            float4 o;
            o.x = acc[i][0] * inv;
            o.y = acc[i][1] * inv;
            o.z = acc[i][2] * inv;
            o.w = acc[i][3] * inv;
            *(float4*)&out[(size_t)n * OC + tx * 4] = o;
        }
    }
}

// ---------------------------------------------------------------- launch
extern "C" void kernel_launch(void* const* d_in, const int* in_sizes, int n_in,
                              void* d_out, int out_size) {
    const float* x  = (const float*)d_in[0];   // [N, 128]
    const float* H  = (const float*)d_in[1];   // [N, E]
    const float* th = (const float*)d_in[2];   // [128, 64]
    float* out = (float*)d_out;                // [N, 64]

    zero_k<<<(EE * OC + 255) / 256, 256>>>();
    xt_k<<<NN / 4, 256>>>(x, th);
    dim3 g2((EE + 63) / 64, SPLIT);
    pass2_k<<<g2, 256>>>(H);
    div_k<<<(EE * OC + 255) / 256, 256>>>();
    pass3_k<<<(NN + 63) / 64, 256>>>(H, out);
}